// round 13
// baseline (speedup 1.0000x reference)
#include <cuda_runtime.h>
#include <cuda_bf16.h>

#define NN 100000
#define NE 1600000
#define D 64
#define EPS 1e-5f
#define CAP 32                 // bucket capacity/row; overflow handled exactly via side list
#define OVF_CAP 8192

// Scratch (__device__ globals; zero-initialized at module load). Total ~26.1MB.
__device__ int   g_cnt[NN];                    // per-row edge count (zeroed by bn)
__device__ int2  g_edge[(size_t)NN * CAP];     // bucketed edges: (col, val-bits), 25.6MB
__device__ int   g_ovfcnt;                     // overflow count (zeroed by bn)
__device__ int   g_ovfr[OVF_CAP];              // overflow rows
__device__ int2  g_ovfe[OVF_CAP];              // overflow edges
__device__ float g_sum[D];
__device__ float g_sq[D];

// Packed fp32x2 helpers (FFMA2 only reachable via PTX)
#define FMA2(d, a, b, c) asm("fma.rn.f32x2 %0, %1, %2, %3;" : "=l"(d) : "l"(a), "l"(b), "l"(c))
#define PACK2U(d, lo, hi) asm("mov.b64 %0, {%1, %2};" : "=l"(d) : "r"(lo), "r"(hi))
#define UNPACK2U(lo, hi, v) asm("mov.b64 {%0, %1}, %2;" : "=r"(lo), "=r"(hi) : "l"(v))

// ---------------------------------------------------------------------------
// 1) Bucket scatter: ONE pass over edges. slot = atomicAdd(cnt[row]).
//    Rare overflow (deg > CAP) goes to an exact side list.
//    Also zeroes BN stats (first block).
// ---------------------------------------------------------------------------
__global__ void scatter_kernel(const float* __restrict__ val,
                               const int*   __restrict__ row,
                               const int*   __restrict__ col) {
    int t = blockIdx.x * blockDim.x + threadIdx.x;
    if (blockIdx.x == 0 && threadIdx.x < D) { g_sum[threadIdx.x] = 0.f; g_sq[threadIdx.x] = 0.f; }
    if (t >= NE / 4) return;
    int4   r4 = ((const int4*)row)[t];
    int4   c4 = ((const int4*)col)[t];
    float4 v4 = ((const float4*)val)[t];

    int s0 = atomicAdd(&g_cnt[r4.x], 1);
    int s1 = atomicAdd(&g_cnt[r4.y], 1);
    int s2 = atomicAdd(&g_cnt[r4.z], 1);
    int s3 = atomicAdd(&g_cnt[r4.w], 1);

    int2 e0 = make_int2(c4.x, __float_as_int(v4.x));
    int2 e1 = make_int2(c4.y, __float_as_int(v4.y));
    int2 e2 = make_int2(c4.z, __float_as_int(v4.z));
    int2 e3 = make_int2(c4.w, __float_as_int(v4.w));

    if (s0 < CAP) g_edge[(size_t)r4.x * CAP + s0] = e0;
    else { int o = atomicAdd(&g_ovfcnt, 1); if (o < OVF_CAP) { g_ovfr[o] = r4.x; g_ovfe[o] = e0; } }
    if (s1 < CAP) g_edge[(size_t)r4.y * CAP + s1] = e1;
    else { int o = atomicAdd(&g_ovfcnt, 1); if (o < OVF_CAP) { g_ovfr[o] = r4.y; g_ovfe[o] = e1; } }
    if (s2 < CAP) g_edge[(size_t)r4.z * CAP + s2] = e2;
    else { int o = atomicAdd(&g_ovfcnt, 1); if (o < OVF_CAP) { g_ovfr[o] = r4.z; g_ovfe[o] = e2; } }
    if (s3 < CAP) g_edge[(size_t)r4.w * CAP + s3] = e3;
    else { int o = atomicAdd(&g_ovfcnt, 1); if (o < OVF_CAP) { g_ovfr[o] = r4.w; g_ovfe[o] = e3; } }
}

// ---------------------------------------------------------------------------
// 2) Fused: h = A@x (bucket gather, 8 rows/warp) ; y = h@W^T + x ; BN stats.
//    Bias dropped (BN batch stats are invariant to constant column shift).
// ---------------------------------------------------------------------------
__global__ void __launch_bounds__(256) fused_kernel(const float* __restrict__ x,
                                                    const float* __restrict__ W,
                                                    float* __restrict__ y) {
    // Wp[p*32+l] = (Wt[2p][2l], Wt[2p][2l+1], Wt[2p+1][2l], Wt[2p+1][2l+1])
    __shared__ float4 Wp[32 * 32];     // 16KB
    __shared__ float4 Hs[8][160];      // padded: logical 128 float4 per warp
    __shared__ float  rs[D];
    __shared__ float  rq[D];

    int tid = threadIdx.x;
    for (int idx = tid; idx < 1024; idx += 256) {
        int p = idx >> 5, l = idx & 31;
        Wp[idx] = make_float4(W[(2 * l) * D + 2 * p],     W[(2 * l + 1) * D + 2 * p],
                              W[(2 * l) * D + 2 * p + 1], W[(2 * l + 1) * D + 2 * p + 1]);
    }
    if (tid < D) { rs[tid] = 0.f; rq[tid] = 0.f; }
    __syncthreads();

    int w = tid >> 5;
    int lane = tid & 31;
    const unsigned long long* xb8 = (const unsigned long long*)x;  // (x[2l],x[2l+1])
    const ulonglong2* Wp2 = (const ulonglong2*)Wp;
    float4* Hw = Hs[w];
    const int novf = min(g_ovfcnt, OVF_CAP);   // 0 in practice

    float s0 = 0.f, s1 = 0.f, q0 = 0.f, q1 = 0.f;
    const int ngroups = NN / 8;        // 12500

    for (int g = blockIdx.x * 8 + w; g < ngroups; g += gridDim.x * 8) {
        int r0 = g * 8;

        // --- gather 8 rows; lane accumulates its 2 columns per row ---
        float hx[8], hy[8];
        #pragma unroll
        for (int rr = 0; rr < 8; rr++) {
            int r = r0 + rr;
            int cnt = g_cnt[r];
            if (cnt > CAP) cnt = CAP;
            int start = r * CAP;               // 256B-aligned bucket row
            int end   = start + cnt;
            unsigned long long hp = 0ull;      // packed (hx,hy)
            int j = start;
            int end8 = start + (cnt & ~7);
            for (; j < end8; j += 8) {
                int2 e[8];
                #pragma unroll
                for (int u = 0; u < 8; u++) e[u] = g_edge[j + u];
                unsigned long long xv[8];
                #pragma unroll
                for (int u = 0; u < 8; u++)
                    xv[u] = xb8[(size_t)e[u].x * 32 + lane];
                #pragma unroll
                for (int u = 0; u < 8; u++) {
                    unsigned long long vv;
                    PACK2U(vv, e[u].y, e[u].y);
                    FMA2(hp, vv, xv[u], hp);
                }
            }
            for (; j < end; j++) {
                int2 e0 = g_edge[j];
                unsigned long long x0 = xb8[(size_t)e0.x * 32 + lane];
                unsigned long long vv;
                PACK2U(vv, e0.y, e0.y);
                FMA2(hp, vv, x0, hp);
            }
            if (novf > 0) {                    // exact overflow merge (tiny list)
                for (int o = 0; o < novf; o++) {
                    if (g_ovfr[o] == r) {
                        int2 e0 = g_ovfe[o];
                        unsigned long long x0 = xb8[(size_t)e0.x * 32 + lane];
                        unsigned long long vv;
                        PACK2U(vv, e0.y, e0.y);
                        FMA2(hp, vv, x0, hp);
                    }
                }
            }
            unsigned ulo, uhi;
            UNPACK2U(ulo, uhi, hp);
            hx[rr] = __uint_as_float(ulo);
            hy[rr] = __uint_as_float(uhi);
        }
        // transpose to smem
        Hw[5 * lane + 0] = make_float4(hx[0], hx[1], hx[2], hx[3]);  // col 2l, r0-3
        Hw[5 * lane + 1] = make_float4(hx[4], hx[5], hx[6], hx[7]);  // col 2l, r4-7
        Hw[5 * lane + 2] = make_float4(hy[0], hy[1], hy[2], hy[3]);  // col 2l+1
        Hw[5 * lane + 3] = make_float4(hy[4], hy[5], hy[6], hy[7]);
        __syncwarp();

        // --- GEMM: acc[r] = packed cols (2l, 2l+1) of output row r0+r ---
        unsigned long long acc[8];
        #pragma unroll
        for (int rr = 0; rr < 8; rr++)
            acc[rr] = xb8[(size_t)(r0 + rr) * 32 + lane];   // residual seed

        #pragma unroll
        for (int p = 0; p < 32; p++) {
            ulonglong2 wv = Wp2[p * 32 + lane];   // .x: k=2p pair, .y: k=2p+1 pair
            float4 alo = Hw[5 * p + 0];
            float4 ahi = Hw[5 * p + 1];
            float4 blo = Hw[5 * p + 2];
            float4 bhi = Hw[5 * p + 3];
            unsigned long long dd;
            unsigned u;
            u = __float_as_uint(alo.x); PACK2U(dd, u, u); FMA2(acc[0], dd, wv.x, acc[0]);
            u = __float_as_uint(blo.x); PACK2U(dd, u, u); FMA2(acc[0], dd, wv.y, acc[0]);
            u = __float_as_uint(alo.y); PACK2U(dd, u, u); FMA2(acc[1], dd, wv.x, acc[1]);
            u = __float_as_uint(blo.y); PACK2U(dd, u, u); FMA2(acc[1], dd, wv.y, acc[1]);
            u = __float_as_uint(alo.z); PACK2U(dd, u, u); FMA2(acc[2], dd, wv.x, acc[2]);
            u = __float_as_uint(blo.z); PACK2U(dd, u, u); FMA2(acc[2], dd, wv.y, acc[2]);
            u = __float_as_uint(alo.w); PACK2U(dd, u, u); FMA2(acc[3], dd, wv.x, acc[3]);
            u = __float_as_uint(blo.w); PACK2U(dd, u, u); FMA2(acc[3], dd, wv.y, acc[3]);
            u = __float_as_uint(ahi.x); PACK2U(dd, u, u); FMA2(acc[4], dd, wv.x, acc[4]);
            u = __float_as_uint(bhi.x); PACK2U(dd, u, u); FMA2(acc[4], dd, wv.y, acc[4]);
            u = __float_as_uint(ahi.y); PACK2U(dd, u, u); FMA2(acc[5], dd, wv.x, acc[5]);
            u = __float_as_uint(bhi.y); PACK2U(dd, u, u); FMA2(acc[5], dd, wv.y, acc[5]);
            u = __float_as_uint(ahi.z); PACK2U(dd, u, u); FMA2(acc[6], dd, wv.x, acc[6]);
            u = __float_as_uint(bhi.z); PACK2U(dd, u, u); FMA2(acc[6], dd, wv.y, acc[6]);
            u = __float_as_uint(ahi.w); PACK2U(dd, u, u); FMA2(acc[7], dd, wv.x, acc[7]);
            u = __float_as_uint(bhi.w); PACK2U(dd, u, u); FMA2(acc[7], dd, wv.y, acc[7]);
        }

        #pragma unroll
        for (int rr = 0; rr < 8; rr++) {
            unsigned ulo, uhi;
            UNPACK2U(ulo, uhi, acc[rr]);
            float o0 = __uint_as_float(ulo);
            float o1 = __uint_as_float(uhi);
            ((float2*)y)[(size_t)(r0 + rr) * 32 + lane] = make_float2(o0, o1);
            s0 += o0; s1 += o1;
            q0 = fmaf(o0, o0, q0);
            q1 = fmaf(o1, o1, q1);
        }
        __syncwarp();
    }

    atomicAdd(&rs[2 * lane],     s0);
    atomicAdd(&rs[2 * lane + 1], s1);
    atomicAdd(&rq[2 * lane],     q0);
    atomicAdd(&rq[2 * lane + 1], q1);
    __syncthreads();
    if (tid < D) {
        atomicAdd(&g_sum[tid], rs[tid]);
        atomicAdd(&g_sq[tid],  rq[tid]);
    }
}

// ---------------------------------------------------------------------------
// 3) BatchNorm + ReLU in-place; also resets g_cnt / g_ovfcnt for next replay
// ---------------------------------------------------------------------------
__global__ void bn_kernel(const float* __restrict__ gamma,
                          const float* __restrict__ beta,
                          float* __restrict__ y) {
    __shared__ float sc[D];
    __shared__ float sh[D];
    int tid = threadIdx.x;
    int gtid = blockIdx.x * blockDim.x + tid;
    const int stride = gridDim.x * blockDim.x;

    // reset counters for next graph replay (no readers until next scatter)
    for (int i = gtid; i < NN; i += stride) g_cnt[i] = 0;
    if (gtid == 0) g_ovfcnt = 0;

    if (tid < D) {
        const float invN = 1.0f / (float)NN;
        float mean = g_sum[tid] * invN;
        float var  = g_sq[tid] * invN - mean * mean;
        float s = gamma[tid] * rsqrtf(var + EPS);
        sc[tid] = s;
        sh[tid] = beta[tid] - mean * s;
    }
    __syncthreads();

    const int total4 = NN * D / 4;                 // 1.6M
    float4 v[4];
    int id[4];
    #pragma unroll
    for (int u = 0; u < 4; u++) {
        id[u] = gtid + u * stride;
        if (id[u] < total4) v[u] = ((float4*)y)[id[u]];
    }
    #pragma unroll
    for (int u = 0; u < 4; u++) {
        if (id[u] < total4) {
            int c = (id[u] * 4) & 63;
            float4 t = v[u];
            t.x = fmaxf(fmaf(t.x, sc[c],     sh[c]),     0.f);
            t.y = fmaxf(fmaf(t.y, sc[c + 1], sh[c + 1]), 0.f);
            t.z = fmaxf(fmaf(t.z, sc[c + 2], sh[c + 2]), 0.f);
            t.w = fmaxf(fmaf(t.w, sc[c + 3], sh[c + 3]), 0.f);
            ((float4*)y)[id[u]] = t;
        }
    }
}

// ---------------------------------------------------------------------------
// Launch. Input order: x, adj_val, W, b, gamma, beta, adj_row, adj_col
// ---------------------------------------------------------------------------
extern "C" void kernel_launch(void* const* d_in, const int* in_sizes, int n_in,
                              void* d_out, int out_size) {
    const float* x       = (const float*)d_in[0];
    const float* adj_val = (const float*)d_in[1];
    const float* W       = (const float*)d_in[2];
    const float* gamma   = (const float*)d_in[4];
    const float* beta    = (const float*)d_in[5];
    const int*   adj_row = (const int*)d_in[6];
    const int*   adj_col = (const int*)d_in[7];
    float* y = (float*)d_out;

    scatter_kernel<<<(NE / 4 + 255) / 256, 256>>>(adj_val, adj_row, adj_col);
    fused_kernel<<<592, 256>>>(x, W, y);
    {
        int total4 = NN * D / 4;
        int blocks = (total4 / 4 + 255) / 256;     // 4 float4 per thread
        bn_kernel<<<blocks, 256>>>(gamma, beta, y);
    }
}

// round 15
// speedup vs baseline: 1.3425x; 1.3425x over previous
#include <cuda_runtime.h>
#include <cuda_bf16.h>

#define NN 100000
#define NE 1600000
#define D 64
#define EPS 1e-5f
#define CAP 32                 // bucket capacity/row; overflow handled exactly via side list
#define OVF_CAP 8192

// Scratch (__device__ globals; zero-initialized at module load). Total ~26.1MB.
__device__ int   g_cnt[NN];                    // per-row edge count (zeroed by bn)
__device__ int2  g_edge[(size_t)NN * CAP];     // bucketed edges: (col, val-bits), 25.6MB
__device__ int   g_ovfcnt;                     // overflow count (zeroed by bn)
__device__ int   g_ovfr[OVF_CAP];              // overflow rows
__device__ int2  g_ovfe[OVF_CAP];              // overflow edges
__device__ float g_sum[D];
__device__ float g_sq[D];

// Packed fp32x2 helpers (FFMA2 only reachable via PTX)
#define FMA2(d, a, b, c) asm("fma.rn.f32x2 %0, %1, %2, %3;" : "=l"(d) : "l"(a), "l"(b), "l"(c))
#define PACK2U(d, lo, hi) asm("mov.b64 %0, {%1, %2};" : "=l"(d) : "r"(lo), "r"(hi))
#define UNPACK2U(lo, hi, v) asm("mov.b64 {%0, %1}, %2;" : "=r"(lo), "=r"(hi) : "l"(v))

// ---------------------------------------------------------------------------
// 1) Bucket scatter: ONE pass over edges. slot = atomicAdd(cnt[row]).
//    Rare overflow (deg > CAP) goes to an exact side list.
//    Also zeroes BN stats (first block).
// ---------------------------------------------------------------------------
__global__ void scatter_kernel(const float* __restrict__ val,
                               const int*   __restrict__ row,
                               const int*   __restrict__ col) {
    int t = blockIdx.x * blockDim.x + threadIdx.x;
    if (blockIdx.x == 0 && threadIdx.x < D) { g_sum[threadIdx.x] = 0.f; g_sq[threadIdx.x] = 0.f; }
    if (t >= NE / 4) return;
    int4   r4 = ((const int4*)row)[t];
    int4   c4 = ((const int4*)col)[t];
    float4 v4 = ((const float4*)val)[t];

    int s0 = atomicAdd(&g_cnt[r4.x], 1);
    int s1 = atomicAdd(&g_cnt[r4.y], 1);
    int s2 = atomicAdd(&g_cnt[r4.z], 1);
    int s3 = atomicAdd(&g_cnt[r4.w], 1);

    int2 e0 = make_int2(c4.x, __float_as_int(v4.x));
    int2 e1 = make_int2(c4.y, __float_as_int(v4.y));
    int2 e2 = make_int2(c4.z, __float_as_int(v4.z));
    int2 e3 = make_int2(c4.w, __float_as_int(v4.w));

    if (s0 < CAP) g_edge[(size_t)r4.x * CAP + s0] = e0;
    else { int o = atomicAdd(&g_ovfcnt, 1); if (o < OVF_CAP) { g_ovfr[o] = r4.x; g_ovfe[o] = e0; } }
    if (s1 < CAP) g_edge[(size_t)r4.y * CAP + s1] = e1;
    else { int o = atomicAdd(&g_ovfcnt, 1); if (o < OVF_CAP) { g_ovfr[o] = r4.y; g_ovfe[o] = e1; } }
    if (s2 < CAP) g_edge[(size_t)r4.z * CAP + s2] = e2;
    else { int o = atomicAdd(&g_ovfcnt, 1); if (o < OVF_CAP) { g_ovfr[o] = r4.z; g_ovfe[o] = e2; } }
    if (s3 < CAP) g_edge[(size_t)r4.w * CAP + s3] = e3;
    else { int o = atomicAdd(&g_ovfcnt, 1); if (o < OVF_CAP) { g_ovfr[o] = r4.w; g_ovfe[o] = e3; } }
}

// ---------------------------------------------------------------------------
// 2) Fused: h = A@x (bucket gather, 8 rows/warp) ; y = h@W^T + x ; BN stats.
//    Overflow scan gated per-row on cnt > CAP (runs for ~10 rows total).
// ---------------------------------------------------------------------------
__global__ void __launch_bounds__(256) fused_kernel(const float* __restrict__ x,
                                                    const float* __restrict__ W,
                                                    float* __restrict__ y) {
    // Wp[p*32+l] = (Wt[2p][2l], Wt[2p][2l+1], Wt[2p+1][2l], Wt[2p+1][2l+1])
    __shared__ float4 Wp[32 * 32];     // 16KB
    __shared__ float4 Hs[8][160];      // padded: logical 128 float4 per warp
    __shared__ float  rs[D];
    __shared__ float  rq[D];

    int tid = threadIdx.x;
    for (int idx = tid; idx < 1024; idx += 256) {
        int p = idx >> 5, l = idx & 31;
        Wp[idx] = make_float4(W[(2 * l) * D + 2 * p],     W[(2 * l + 1) * D + 2 * p],
                              W[(2 * l) * D + 2 * p + 1], W[(2 * l + 1) * D + 2 * p + 1]);
    }
    if (tid < D) { rs[tid] = 0.f; rq[tid] = 0.f; }
    __syncthreads();

    int w = tid >> 5;
    int lane = tid & 31;
    const unsigned long long* xb8 = (const unsigned long long*)x;  // (x[2l],x[2l+1])
    const ulonglong2* Wp2 = (const ulonglong2*)Wp;
    float4* Hw = Hs[w];
    const int novf = min(g_ovfcnt, OVF_CAP);   // ~0-40 in practice

    float s0 = 0.f, s1 = 0.f, q0 = 0.f, q1 = 0.f;
    const int ngroups = NN / 8;        // 12500

    for (int g = blockIdx.x * 8 + w; g < ngroups; g += gridDim.x * 8) {
        int r0 = g * 8;

        // counts for the 8 contiguous rows: two broadcast int4 loads (32B-aligned)
        int4 ca4 = ((const int4*)&g_cnt[r0])[0];
        int4 cb4 = ((const int4*)&g_cnt[r0])[1];
        int cnts[8] = {ca4.x, ca4.y, ca4.z, ca4.w, cb4.x, cb4.y, cb4.z, cb4.w};

        // --- gather 8 rows; lane accumulates its 2 columns per row ---
        float hx[8], hy[8];
        #pragma unroll
        for (int rr = 0; rr < 8; rr++) {
            int r = r0 + rr;
            int rawcnt = cnts[rr];
            int cnt = rawcnt > CAP ? CAP : rawcnt;
            int start = r * CAP;               // 256B-aligned bucket row
            int end   = start + cnt;
            unsigned long long hp = 0ull;      // packed (hx,hy)
            int j = start;
            int end8 = start + (cnt & ~7);
            for (; j < end8; j += 8) {
                int2 e[8];
                #pragma unroll
                for (int u = 0; u < 8; u++) e[u] = g_edge[j + u];
                unsigned long long xv[8];
                #pragma unroll
                for (int u = 0; u < 8; u++)
                    xv[u] = xb8[(size_t)e[u].x * 32 + lane];
                #pragma unroll
                for (int u = 0; u < 8; u++) {
                    unsigned long long vv;
                    PACK2U(vv, e[u].y, e[u].y);
                    FMA2(hp, vv, xv[u], hp);
                }
            }
            for (; j < end; j++) {
                int2 e0 = g_edge[j];
                unsigned long long x0 = xb8[(size_t)e0.x * 32 + lane];
                unsigned long long vv;
                PACK2U(vv, e0.y, e0.y);
                FMA2(hp, vv, x0, hp);
            }
            if (rawcnt > CAP) {                // exact overflow merge — ~10 rows globally
                #pragma unroll 1
                for (int o = 0; o < novf; o++) {
                    if (g_ovfr[o] == r) {
                        int2 e0 = g_ovfe[o];
                        unsigned long long x0 = xb8[(size_t)e0.x * 32 + lane];
                        unsigned long long vv;
                        PACK2U(vv, e0.y, e0.y);
                        FMA2(hp, vv, x0, hp);
                    }
                }
            }
            unsigned ulo, uhi;
            UNPACK2U(ulo, uhi, hp);
            hx[rr] = __uint_as_float(ulo);
            hy[rr] = __uint_as_float(uhi);
        }
        // transpose to smem
        Hw[5 * lane + 0] = make_float4(hx[0], hx[1], hx[2], hx[3]);  // col 2l, r0-3
        Hw[5 * lane + 1] = make_float4(hx[4], hx[5], hx[6], hx[7]);  // col 2l, r4-7
        Hw[5 * lane + 2] = make_float4(hy[0], hy[1], hy[2], hy[3]);  // col 2l+1
        Hw[5 * lane + 3] = make_float4(hy[4], hy[5], hy[6], hy[7]);
        __syncwarp();

        // --- GEMM: acc[r] = packed cols (2l, 2l+1) of output row r0+r ---
        unsigned long long acc[8];
        #pragma unroll
        for (int rr = 0; rr < 8; rr++)
            acc[rr] = xb8[(size_t)(r0 + rr) * 32 + lane];   // residual seed

        #pragma unroll
        for (int p = 0; p < 32; p++) {
            ulonglong2 wv = Wp2[p * 32 + lane];   // .x: k=2p pair, .y: k=2p+1 pair
            float4 alo = Hw[5 * p + 0];
            float4 ahi = Hw[5 * p + 1];
            float4 blo = Hw[5 * p + 2];
            float4 bhi = Hw[5 * p + 3];
            unsigned long long dd;
            unsigned u;
            u = __float_as_uint(alo.x); PACK2U(dd, u, u); FMA2(acc[0], dd, wv.x, acc[0]);
            u = __float_as_uint(blo.x); PACK2U(dd, u, u); FMA2(acc[0], dd, wv.y, acc[0]);
            u = __float_as_uint(alo.y); PACK2U(dd, u, u); FMA2(acc[1], dd, wv.x, acc[1]);
            u = __float_as_uint(blo.y); PACK2U(dd, u, u); FMA2(acc[1], dd, wv.y, acc[1]);
            u = __float_as_uint(alo.z); PACK2U(dd, u, u); FMA2(acc[2], dd, wv.x, acc[2]);
            u = __float_as_uint(blo.z); PACK2U(dd, u, u); FMA2(acc[2], dd, wv.y, acc[2]);
            u = __float_as_uint(alo.w); PACK2U(dd, u, u); FMA2(acc[3], dd, wv.x, acc[3]);
            u = __float_as_uint(blo.w); PACK2U(dd, u, u); FMA2(acc[3], dd, wv.y, acc[3]);
            u = __float_as_uint(ahi.x); PACK2U(dd, u, u); FMA2(acc[4], dd, wv.x, acc[4]);
            u = __float_as_uint(bhi.x); PACK2U(dd, u, u); FMA2(acc[4], dd, wv.y, acc[4]);
            u = __float_as_uint(ahi.y); PACK2U(dd, u, u); FMA2(acc[5], dd, wv.x, acc[5]);
            u = __float_as_uint(bhi.y); PACK2U(dd, u, u); FMA2(acc[5], dd, wv.y, acc[5]);
            u = __float_as_uint(ahi.z); PACK2U(dd, u, u); FMA2(acc[6], dd, wv.x, acc[6]);
            u = __float_as_uint(bhi.z); PACK2U(dd, u, u); FMA2(acc[6], dd, wv.y, acc[6]);
            u = __float_as_uint(ahi.w); PACK2U(dd, u, u); FMA2(acc[7], dd, wv.x, acc[7]);
            u = __float_as_uint(bhi.w); PACK2U(dd, u, u); FMA2(acc[7], dd, wv.y, acc[7]);
        }

        #pragma unroll
        for (int rr = 0; rr < 8; rr++) {
            unsigned ulo, uhi;
            UNPACK2U(ulo, uhi, acc[rr]);
            float o0 = __uint_as_float(ulo);
            float o1 = __uint_as_float(uhi);
            ((float2*)y)[(size_t)(r0 + rr) * 32 + lane] = make_float2(o0, o1);
            s0 += o0; s1 += o1;
            q0 = fmaf(o0, o0, q0);
            q1 = fmaf(o1, o1, q1);
        }
        __syncwarp();
    }

    atomicAdd(&rs[2 * lane],     s0);
    atomicAdd(&rs[2 * lane + 1], s1);
    atomicAdd(&rq[2 * lane],     q0);
    atomicAdd(&rq[2 * lane + 1], q1);
    __syncthreads();
    if (tid < D) {
        atomicAdd(&g_sum[tid], rs[tid]);
        atomicAdd(&g_sq[tid],  rq[tid]);
    }
}

// ---------------------------------------------------------------------------
// 3) BatchNorm + ReLU in-place; also resets g_cnt / g_ovfcnt for next replay
// ---------------------------------------------------------------------------
__global__ void bn_kernel(const float* __restrict__ gamma,
                          const float* __restrict__ beta,
                          float* __restrict__ y) {
    __shared__ float sc[D];
    __shared__ float sh[D];
    int tid = threadIdx.x;
    int gtid = blockIdx.x * blockDim.x + tid;
    const int stride = gridDim.x * blockDim.x;

    // reset counters for next graph replay (no readers until next scatter)
    for (int i = gtid; i < NN; i += stride) g_cnt[i] = 0;
    if (gtid == 0) g_ovfcnt = 0;

    if (tid < D) {
        const float invN = 1.0f / (float)NN;
        float mean = g_sum[tid] * invN;
        float var  = g_sq[tid] * invN - mean * mean;
        float s = gamma[tid] * rsqrtf(var + EPS);
        sc[tid] = s;
        sh[tid] = beta[tid] - mean * s;
    }
    __syncthreads();

    const int total4 = NN * D / 4;                 // 1.6M
    float4 v[4];
    int id[4];
    #pragma unroll
    for (int u = 0; u < 4; u++) {
        id[u] = gtid + u * stride;
        if (id[u] < total4) v[u] = ((float4*)y)[id[u]];
    }
    #pragma unroll
    for (int u = 0; u < 4; u++) {
        if (id[u] < total4) {
            int c = (id[u] * 4) & 63;
            float4 t = v[u];
            t.x = fmaxf(fmaf(t.x, sc[c],     sh[c]),     0.f);
            t.y = fmaxf(fmaf(t.y, sc[c + 1], sh[c + 1]), 0.f);
            t.z = fmaxf(fmaf(t.z, sc[c + 2], sh[c + 2]), 0.f);
            t.w = fmaxf(fmaf(t.w, sc[c + 3], sh[c + 3]), 0.f);
            ((float4*)y)[id[u]] = t;
        }
    }
}

// ---------------------------------------------------------------------------
// Launch. Input order: x, adj_val, W, b, gamma, beta, adj_row, adj_col
// ---------------------------------------------------------------------------
extern "C" void kernel_launch(void* const* d_in, const int* in_sizes, int n_in,
                              void* d_out, int out_size) {
    const float* x       = (const float*)d_in[0];
    const float* adj_val = (const float*)d_in[1];
    const float* W       = (const float*)d_in[2];
    const float* gamma   = (const float*)d_in[4];
    const float* beta    = (const float*)d_in[5];
    const int*   adj_row = (const int*)d_in[6];
    const int*   adj_col = (const int*)d_in[7];
    float* y = (float*)d_out;

    scatter_kernel<<<(NE / 4 + 255) / 256, 256>>>(adj_val, adj_row, adj_col);
    fused_kernel<<<592, 256>>>(x, W, y);
    {
        int total4 = NN * D / 4;
        int blocks = (total4 / 4 + 255) / 256;     // 4 float4 per thread
        bn_kernel<<<blocks, 256>>>(gamma, beta, y);
    }
}